// round 14
// baseline (speedup 1.0000x reference)
#include <cuda_runtime.h>

typedef unsigned long long ull;

#define LOG2E 1.4426950408889634f
#define BB 32
#define NN 512
#define NH 8
#define ND 8
#define NF 128
#define KEYMASK 0xFFFFFE00u

// ---------------- scratch ----------------
__device__ float g_x[BB * NN * NH * ND];     // layer-1 output, [b][n][h*8+d]

// ---------------- helpers ----------------
__device__ __forceinline__ float ex2f(float x) {
    float r; asm("ex2.approx.f32 %0, %1;" : "=f"(r) : "f"(x)); return r;
}
__device__ __forceinline__ void ffma2(ull &acc, ull a, ull b) {
    asm("fma.rn.f32x2 %0, %1, %2, %0;" : "+l"(acc) : "l"(a), "l"(b));
}
__device__ __forceinline__ ull packf2(float lo, float hi) {
    ull r; asm("mov.b64 %0, {%1, %2};" : "=l"(r) : "f"(lo), "f"(hi)); return r;
}
__device__ __forceinline__ float lof(ull v) { return __uint_as_float((unsigned)(v & 0xffffffffu)); }
__device__ __forceinline__ float hif(ull v) { return __uint_as_float((unsigned)(v >> 32)); }
__device__ __forceinline__ float lrelu02(float x) { return fmaxf(x, 0.2f * x); }
__device__ __forceinline__ float eluf(float x) { return x > 0.f ? x : ex2f(x * LOG2E) - 1.0f; }
__device__ __forceinline__ unsigned f2s(float f) {
    unsigned u = __float_as_uint(f);
    return u ^ ((u & 0x80000000u) ? 0xFFFFFFFFu : 0x80000000u);
}
// lower_bound over 512 sorted u32 (10 steps, result in [0,512])
__device__ __forceinline__ int lb512(const unsigned* arr, unsigned X) {
    int c = 0;
#pragma unroll
    for (int s = 512; s >= 1; s >>= 1) {
        int t = c + s;
        if (t <= 512 && arr[t - 1] < X) c = t;
    }
    return c;
}

// =====================================================================
// kB: fused projection + layer-1 attention per (b,h).
// grid (32, 8), 512 threads, 2 blocks/SM.
// Projection: W_h staged pre-paired over k (broadcast LDS), nf via LDG.
// Attention: branch-factorized softmax (sort + prefix-scan), as before.
// =====================================================================
struct K2S {
    float SUV[16 * 640];        // comp-major, 32 chunks x (16 data + 4 pad)
    ull sbuf[2][NN];            // packed (keyA<<32 | keyB) cross-warp exchange
    ull Wp[512];                // pre-paired W_h: Wp[k2*8+d] = (W[2k2][d], W[2k2+1][d])
    unsigned sortedA[NN];
    unsigned sortedB[NN];
    float E1s[NN], F1s[NN];
    float PE[NN], PF[NN];
    float wsum2[16][2], off2[16][2];
    float redbuf[16];
    float av[16];
    unsigned short rankB[NN];
};
__device__ __forceinline__ int suv_addr(int c, int r) {
    return c * 640 + (r >> 4) * 20 + (r & 15);
}

__device__ __forceinline__ void scan2b(float* A, float* B, float (*wsum2)[2],
                                       float (*off2)[2], int tid) {
    const int lane = tid & 31, wid = tid >> 5;
    float a = A[tid], b = B[tid];
#pragma unroll
    for (int s = 1; s < 32; s <<= 1) {
        float ta = __shfl_up_sync(0xffffffffu, a, s);
        float tb = __shfl_up_sync(0xffffffffu, b, s);
        if (lane >= s) { a += ta; b += tb; }
    }
    if (lane == 31) { wsum2[wid][0] = a; wsum2[wid][1] = b; }
    __syncthreads();
    if (wid < 2) {
        float x0 = (lane < 16) ? wsum2[lane][wid] : 0.f;
        float x = x0;
#pragma unroll
        for (int s = 1; s < 16; s <<= 1) {
            float tv = __shfl_up_sync(0xffffffffu, x, s);
            if (lane >= s) x += tv;
        }
        if (lane < 16) off2[lane][wid] = x - x0;
    }
    __syncthreads();
    A[tid] = a + off2[wid][0];
    B[tid] = b + off2[wid][1];
    __syncthreads();
}

__global__ __launch_bounds__(512, 2) void kB(const float* __restrict__ nf,
                                             const float* __restrict__ Ws_g,
                                             const float* __restrict__ As_g) {
    extern __shared__ char raw[];
    K2S& S = *reinterpret_cast<K2S*>(raw);
    const int b = blockIdx.x, h = blockIdx.y, tid = threadIdx.x;
    const int lane = tid & 31, wid = tid >> 5;

    // ---- stage pre-paired W_h and attention vector ----
    {
        int k2 = tid >> 3, d = tid & 7;
        const float* wsrc = Ws_g + h * 1024 + (2 * k2) * 8 + d;
        S.Wp[tid] = packf2(wsrc[0], wsrc[8]);
    }
    if (tid < 16) S.av[tid] = As_g[h * 16 + tid];
    __syncthreads();

    // ---- projection: wv[0..7] = nf[b, tid, :] @ W_h ----
    const float4* xr = reinterpret_cast<const float4*>(nf + (size_t)(b * NN + tid) * NF);
    ull acc[8];
#pragma unroll
    for (int d = 0; d < 8; d++) acc[d] = 0ull;
#pragma unroll 4
    for (int f4 = 0; f4 < 32; f4++) {
        float4 v = xr[f4];
        ull x0 = packf2(v.x, v.y);     // k2 = 2*f4
        ull x1 = packf2(v.z, v.w);     // k2 = 2*f4+1
        const ulonglong2* w0 = reinterpret_cast<const ulonglong2*>(&S.Wp[(2 * f4) * 8]);
        ulonglong2 p0 = w0[0], p1 = w0[1], p2 = w0[2], p3 = w0[3];
        ffma2(acc[0], x0, p0.x); ffma2(acc[1], x0, p0.y);
        ffma2(acc[2], x0, p1.x); ffma2(acc[3], x0, p1.y);
        ffma2(acc[4], x0, p2.x); ffma2(acc[5], x0, p2.y);
        ffma2(acc[6], x0, p3.x); ffma2(acc[7], x0, p3.y);
        const ulonglong2* w1 = reinterpret_cast<const ulonglong2*>(&S.Wp[(2 * f4 + 1) * 8]);
        ulonglong2 q0 = w1[0], q1 = w1[1], q2 = w1[2], q3 = w1[3];
        ffma2(acc[0], x1, q0.x); ffma2(acc[1], x1, q0.y);
        ffma2(acc[2], x1, q1.x); ffma2(acc[3], x1, q1.y);
        ffma2(acc[4], x1, q2.x); ffma2(acc[5], x1, q2.y);
        ffma2(acc[6], x1, q3.x); ffma2(acc[7], x1, q3.y);
    }
    float wv[8];
#pragma unroll
    for (int d = 0; d < 8; d++) wv[d] = lof(acc[d]) + hif(acc[d]);

    float s1 = 0.f, s2 = 0.f;
#pragma unroll
    for (int d = 0; d < 8; d++) { s1 += wv[d] * S.av[d]; s2 += wv[d] * S.av[8 + d]; }
    const float s1L = s1 * LOG2E, s2L = s2 * LOG2E;

    // ---- block max M of s1L ----
    float m = s1L;
#pragma unroll
    for (int o = 16; o >= 1; o >>= 1) m = fmaxf(m, __shfl_xor_sync(0xffffffffu, m, o));
    if (lane == 0) S.redbuf[wid] = m;
    __syncthreads();
    float M = S.redbuf[0];
#pragma unroll
    for (int w = 1; w < 16; w++) M = fmaxf(M, S.redbuf[w]);

    const float E1 = ex2f(s1L - M);
    const float F1 = ex2f(0.2f * (s1L - M));
    S.E1s[tid] = E1;
    S.F1s[tid] = F1;

    // ---- dual 32-bit truncated-key bitonic sort ----
    unsigned ka = (f2s(s1L) & KEYMASK) | (unsigned)tid;
    unsigned kb = (f2s(s2L) & KEYMASK) | (unsigned)tid;
    int p = 0;
    for (int k = 2; k <= NN; k <<= 1) {
        for (int s = k >> 1; s >= 1; s >>= 1) {
            const bool keepmin = (((tid & s) == 0) == ((tid & k) == 0));
            unsigned oa, ob;
            if (s >= 32) {
                S.sbuf[p][tid] = (((ull)ka) << 32) | kb;
                __syncthreads();
                ull o = S.sbuf[p][tid ^ s];
                oa = (unsigned)(o >> 32); ob = (unsigned)o;
                p ^= 1;
            } else {
                oa = __shfl_xor_sync(0xffffffffu, ka, s);
                ob = __shfl_xor_sync(0xffffffffu, kb, s);
            }
            ka = ((ka < oa) == keepmin) ? ka : oa;
            kb = ((kb < ob) == keepmin) ? kb : ob;
        }
    }
    S.sortedA[tid] = ka;
    S.sortedB[tid] = kb;
    {
        int ja = (int)(ka & 511u);
        int jb = (int)(kb & 511u);
        S.rankB[jb] = (unsigned short)tid;
        S.PE[tid] = S.E1s[ja];
        S.PF[tid] = S.F1s[ja];
    }
    __syncthreads();
    scan2b(S.PE, S.PF, S.wsum2, S.off2, tid);
    const float TE = S.PE[NN - 1];

    // ---- per thread j: Z_j, scatter U/V into sorted-s2 slot ----
    const int c = lb512(S.sortedA, f2s(-s2L) & KEYMASK);
    const float sumEge = TE - (c > 0 ? S.PE[c - 1] : 0.f);
    const float preF   = (c > 0 ? S.PF[c - 1] : 0.f);
    const float mj = lrelu02(M + s2L);
    const float E2 = ex2f(s2L + M - mj);
    const float F2 = ex2f(0.2f * (s2L + M) - mj);
    const float rz = 1.0f / (E2 * sumEge + F2 * preF);
    const float ue = E2 * rz, vf = F2 * rz;

    const int r = S.rankB[tid];
#pragma unroll
    for (int d = 0; d < 8; d++) {
        S.SUV[suv_addr(d, r)]     = ue * wv[d];
        S.SUV[suv_addr(8 + d, r)] = vf * wv[d];
    }
    __syncthreads();

    // ---- warp-per-component scan over 512 rows ----
    {
        float4* base = reinterpret_cast<float4*>(S.SUV) + wid * 160 + lane * 5;
        float4 q0 = base[0], q1 = base[1], q2 = base[2], q3 = base[3];
        float v[16] = {q0.x, q0.y, q0.z, q0.w, q1.x, q1.y, q1.z, q1.w,
                       q2.x, q2.y, q2.z, q2.w, q3.x, q3.y, q3.z, q3.w};
#pragma unroll
        for (int i = 1; i < 16; i++) v[i] += v[i - 1];
        float tot = v[15], inc = tot;
#pragma unroll
        for (int s = 1; s < 32; s <<= 1) {
            float tv = __shfl_up_sync(0xffffffffu, inc, s);
            if (lane >= s) inc += tv;
        }
        float off = inc - tot;
#pragma unroll
        for (int i = 0; i < 16; i++) v[i] += off;
        base[0] = make_float4(v[0], v[1], v[2], v[3]);
        base[1] = make_float4(v[4], v[5], v[6], v[7]);
        base[2] = make_float4(v[8], v[9], v[10], v[11]);
        base[3] = make_float4(v[12], v[13], v[14], v[15]);
    }
    __syncthreads();

    float TU[8];
#pragma unroll
    for (int d = 0; d < 8; d++) TU[d] = S.SUV[suv_addr(d, NN - 1)];

    // ---- per thread i: h_i = E1*SufU + F1*PreV, elu, store ----
    const int c2 = lb512(S.sortedB, f2s(-s1L) & KEYMASK);
    float res[8];
#pragma unroll
    for (int d = 0; d < 8; d++) {
        float su = TU[d] - (c2 > 0 ? S.SUV[suv_addr(d, c2 - 1)] : 0.f);
        float pv = (c2 > 0 ? S.SUV[suv_addr(8 + d, c2 - 1)] : 0.f);
        res[d] = eluf(E1 * su + F1 * pv);
    }
    float4* xo = reinterpret_cast<float4*>(g_x + ((size_t)(b * NN + tid)) * (NH * ND) + h * ND);
    xo[0] = make_float4(res[0], res[1], res[2], res[3]);
    xo[1] = make_float4(res[4], res[5], res[6], res[7]);
}

// =====================================================================
// kCDE: fused layer-2 projection + attention (row 0) + MLP head.
// grid 32 (one block per batch), 512 threads.
// =====================================================================
__global__ __launch_bounds__(512) void kCDE(const float* __restrict__ Wout,
                                            const float* __restrict__ aout,
                                            const float* __restrict__ feats,
                                            const float* __restrict__ lin1w,
                                            const float* __restrict__ lin1b,
                                            const float* __restrict__ prelua,
                                            const float* __restrict__ gamma,
                                            const float* __restrict__ beta,
                                            const float* __restrict__ lin2w,
                                            const float* __restrict__ lin2b,
                                            float* __restrict__ out) {
    __shared__ float Wot[8][72];    // 72*4=288 B ≡ 0 mod 16
    __shared__ float ao[16];
    __shared__ unsigned sbufD[2][NN];
    __shared__ unsigned sortedA[NN];
    __shared__ float E1s[NN], F1s[NN], PE[NN], PF[NN];
    __shared__ float wsum2[16][2], off2[16][2];
    __shared__ float redbuf[16];
    __shared__ float wpart[16][8];
    __shared__ float hsum[8];
    __shared__ float bc0[1];

    const int b = blockIdx.x, tid = threadIdx.x;
    const int lane = tid & 31, wid = tid >> 5;

    Wot[tid & 7][tid >> 3] = Wout[tid];
    if (tid < 16) ao[tid] = aout[tid];
    __syncthreads();

    const float4* xr = reinterpret_cast<const float4*>(g_x + ((size_t)(b * NN + tid)) * 64);
    float4 xv[16];
#pragma unroll
    for (int q = 0; q < 16; q++) xv[q] = xr[q];
    ull xp[32];
#pragma unroll
    for (int q = 0; q < 16; q++) {
        xp[2 * q]     = packf2(xv[q].x, xv[q].y);
        xp[2 * q + 1] = packf2(xv[q].z, xv[q].w);
    }
    float acc[8];
#pragma unroll
    for (int d = 0; d < 8; d++) {
        ull a2 = 0ull;
#pragma unroll
        for (int q = 0; q < 16; q++) {
            float4 bq = *reinterpret_cast<const float4*>(&Wot[d][q * 4]);
            ffma2(a2, xp[2 * q], packf2(bq.x, bq.y));
            ffma2(a2, xp[2 * q + 1], packf2(bq.z, bq.w));
        }
        acc[d] = lof(a2) + hif(a2);
    }
    float s1 = 0.f, s2 = 0.f;
#pragma unroll
    for (int d = 0; d < 8; d++) { s1 += acc[d] * ao[d]; s2 += acc[d] * ao[8 + d]; }
    const float s1L = s1 * LOG2E, s2L = s2 * LOG2E;
    if (tid == 0) bc0[0] = s1L;

    float m = s1L;
#pragma unroll
    for (int o = 16; o >= 1; o >>= 1) m = fmaxf(m, __shfl_xor_sync(0xffffffffu, m, o));
    if (lane == 0) redbuf[wid] = m;
    __syncthreads();
    float M = redbuf[0];
#pragma unroll
    for (int w = 1; w < 16; w++) M = fmaxf(M, redbuf[w]);

    E1s[tid] = ex2f(s1L - M);
    F1s[tid] = ex2f(0.2f * (s1L - M));

    unsigned ka = (f2s(s1L) & KEYMASK) | (unsigned)tid;
    int p = 0;
    for (int k = 2; k <= NN; k <<= 1) {
        for (int s = k >> 1; s >= 1; s >>= 1) {
            const bool keepmin = (((tid & s) == 0) == ((tid & k) == 0));
            unsigned oa;
            if (s >= 32) {
                sbufD[p][tid] = ka;
                __syncthreads();
                oa = sbufD[p][tid ^ s];
                p ^= 1;
            } else {
                oa = __shfl_xor_sync(0xffffffffu, ka, s);
            }
            ka = ((ka < oa) == keepmin) ? ka : oa;
        }
    }
    sortedA[tid] = ka;
    {
        int ja = (int)(ka & 511u);
        PE[tid] = E1s[ja];
        PF[tid] = F1s[ja];
    }
    __syncthreads();
    scan2b(PE, PF, wsum2, off2, tid);
    const float TE = PE[NN - 1];

    const int c = lb512(sortedA, f2s(-s2L) & KEYMASK);
    const float sumEge = TE - (c > 0 ? PE[c - 1] : 0.f);
    const float preF   = (c > 0 ? PF[c - 1] : 0.f);
    const float mj = lrelu02(M + s2L);
    const float E2 = ex2f(s2L + M - mj);
    const float F2 = ex2f(0.2f * (s2L + M) - mj);
    const float Z = E2 * sumEge + F2 * preF;

    const float s1L0 = bc0[0];
    const float e0 = (s1L0 + s2L >= 0.f) ? ex2f(s1L0 - M) * E2
                                         : ex2f(0.2f * (s1L0 - M)) * F2;
    const float wj = e0 / Z;

    float pv[8];
#pragma unroll
    for (int d = 0; d < 8; d++) pv[d] = wj * acc[d];
#pragma unroll
    for (int d = 0; d < 8; d++) {
#pragma unroll
        for (int o = 16; o >= 1; o >>= 1)
            pv[d] += __shfl_xor_sync(0xffffffffu, pv[d], o);
    }
    if (lane == 0) {
#pragma unroll
        for (int d = 0; d < 8; d++) wpart[wid][d] = pv[d];
    }
    __syncthreads();
    if (tid < 8) {
        float s = 0.f;
#pragma unroll
        for (int w = 0; w < 16; w++) s += wpart[w][tid];
        hsum[tid] = eluf(s);
    }
    __syncthreads();

    if (tid < 8) {
        const int k = tid;
        const float* w = lin1w + k * 136;
        const float* fr = feats + b * 128;
        float z = lin1b[k];
#pragma unroll 8
        for (int f = 0; f < 128; f++) z += fr[f] * w[f];
#pragma unroll
        for (int d = 0; d < 8; d++) z += hsum[d] * w[128 + d];
        const float pa = prelua[0];
        z = (z >= 0.f) ? z : pa * z;
        z = z * rsqrtf(1.0f + 1e-5f) * gamma[k] + beta[k];
        float v = z * lin2w[k];
        v += __shfl_xor_sync(0x000000ffu, v, 4);
        v += __shfl_xor_sync(0x000000ffu, v, 2);
        v += __shfl_xor_sync(0x000000ffu, v, 1);
        if (k == 0) out[b] = v + lin2b[0];
    }
}

// =====================================================================
extern "C" void kernel_launch(void* const* d_in, const int* in_sizes, int n_in,
                              void* d_out, int out_size) {
    (void)in_sizes; (void)n_in; (void)out_size;
    const float* feats  = (const float*)d_in[0];
    const float* nf     = (const float*)d_in[1];
    const float* Ws     = (const float*)d_in[2];
    const float* As     = (const float*)d_in[3];
    const float* Wout   = (const float*)d_in[4];
    const float* aout   = (const float*)d_in[5];
    const float* lin1w  = (const float*)d_in[6];
    const float* lin1b  = (const float*)d_in[7];
    const float* prelua = (const float*)d_in[8];
    const float* gamma  = (const float*)d_in[9];
    const float* beta   = (const float*)d_in[10];
    const float* lin2w  = (const float*)d_in[11];
    const float* lin2b  = (const float*)d_in[12];
    float* out = (float*)d_out;

    static bool attr_done = false;
    if (!attr_done) {
        cudaFuncSetAttribute(kB, cudaFuncAttributeMaxDynamicSharedMemorySize,
                             (int)sizeof(K2S));
        attr_done = true;
    }

    kB<<<dim3(32, 8), 512, sizeof(K2S)>>>(nf, Ws, As);
    kCDE<<<32, 512>>>(Wout, aout, feats, lin1w, lin1b, prelua, gamma, beta,
                      lin2w, lin2b, out);
}

// round 15
// speedup vs baseline: 1.3387x; 1.3387x over previous
#include <cuda_runtime.h>

typedef unsigned long long ull;

#define LOG2E 1.4426950408889634f
#define BB 32
#define NN 512
#define NH 8
#define ND 8
#define NF 128
#define KEYMASK 0xFFFFFE00u

// ---------------- scratch ----------------
__device__ float g_Wh1[BB * NH * NN * ND];   // [b][h][n][d]
__device__ float g_x[BB * NN * NH * ND];     // [b][n][h*8+d]
__device__ float g_h0p[BB][4][ND];           // layer-2 per-chunk partials

// ---------------- helpers ----------------
__device__ __forceinline__ float ex2f(float x) {
    float r; asm("ex2.approx.f32 %0, %1;" : "=f"(r) : "f"(x)); return r;
}
__device__ __forceinline__ void ffma2(ull &acc, ull a, ull b) {
    asm("fma.rn.f32x2 %0, %1, %2, %0;" : "+l"(acc) : "l"(a), "l"(b));
}
__device__ __forceinline__ ull packf2(float lo, float hi) {
    ull r; asm("mov.b64 %0, {%1, %2};" : "=l"(r) : "f"(lo), "f"(hi)); return r;
}
__device__ __forceinline__ float lof(ull v) { return __uint_as_float((unsigned)(v & 0xffffffffu)); }
__device__ __forceinline__ float hif(ull v) { return __uint_as_float((unsigned)(v >> 32)); }
__device__ __forceinline__ float lrelu02(float x) { return fmaxf(x, 0.2f * x); }
__device__ __forceinline__ float eluf(float x) { return x > 0.f ? x : ex2f(x * LOG2E) - 1.0f; }
__device__ __forceinline__ unsigned f2s(float f) {
    unsigned u = __float_as_uint(f);
    return u ^ ((u & 0x80000000u) ? 0xFFFFFFFFu : 0x80000000u);
}
__device__ __forceinline__ int lb512(const unsigned* arr, unsigned X) {
    int c = 0;
#pragma unroll
    for (int s = 512; s >= 1; s >>= 1) {
        int t = c + s;
        if (t <= 512 && arr[t - 1] < X) c = t;
    }
    return c;
}

// =====================================================================
// kA: Wh = nf @ W  as [16384,128]@[128,64] GEMM.  (Round-13 version)
// grid 128 (128-row tiles, single wave), 512 threads, 4x4 thread tiles.
// =====================================================================
#define KA_BSTRIDE 10
#define KA_SMEM (128 * 128 * 4 + 32 * 16 * KA_BSTRIDE * 8)
__global__ __launch_bounds__(512) void kA(const float* __restrict__ nf,
                                          const float* __restrict__ Ws) {
    extern __shared__ float sm[];
    float* As = sm;
    ull* Bp = reinterpret_cast<ull*>(sm + 128 * 128);
    const int t = threadIdx.x, blk = blockIdx.x;

    const float4* gA = reinterpret_cast<const float4*>(nf) + (size_t)blk * 128 * 32;
    float4* As4 = reinterpret_cast<float4*>(As);
#pragma unroll
    for (int i = 0; i < 8; i++) {
        int idx4 = t + 512 * i;
        As4[idx4] = gA[idx4];
    }
#pragma unroll
    for (int i = 0; i < 8; i++) {
        int idx = t + 512 * i;
        int k4 = idx >> 7, rem = idx & 127;
        int tx = rem >> 3, s = rem & 7;
        int c = 4 * tx + (s & 3);
        int kk = 4 * k4 + 2 * (s >> 2);
        const float* wsrc = Ws + (c >> 3) * 1024 + kk * 8 + (c & 7);
        Bp[(k4 * 16 + tx) * KA_BSTRIDE + s] = packf2(wsrc[0], wsrc[8]);
    }
    __syncthreads();

    const int tx = t & 15, ty = t >> 4;
    ull acc2[4][4];
#pragma unroll
    for (int r = 0; r < 4; r++)
#pragma unroll
        for (int c = 0; c < 4; c++) acc2[r][c] = 0ull;

#pragma unroll 8
    for (int k4 = 0; k4 < 32; k4++) {
        ull ap[4][2];
#pragma unroll
        for (int r = 0; r < 4; r++) {
            float4 a = *reinterpret_cast<const float4*>(&As[(ty * 4 + r) * 128 + k4 * 4]);
            ap[r][0] = packf2(a.x, a.y);
            ap[r][1] = packf2(a.z, a.w);
        }
        const ull* bb = Bp + (k4 * 16 + tx) * KA_BSTRIDE;
        ulonglong2 u0 = *reinterpret_cast<const ulonglong2*>(bb + 0);
        ulonglong2 u1 = *reinterpret_cast<const ulonglong2*>(bb + 2);
        ulonglong2 u2 = *reinterpret_cast<const ulonglong2*>(bb + 4);
        ulonglong2 u3 = *reinterpret_cast<const ulonglong2*>(bb + 6);
        ull bp01[4] = {u0.x, u0.y, u1.x, u1.y};
        ull bp23[4] = {u2.x, u2.y, u3.x, u3.y};
#pragma unroll
        for (int r = 0; r < 4; r++)
#pragma unroll
            for (int c = 0; c < 4; c++) {
                ffma2(acc2[r][c], ap[r][0], bp01[c]);
                ffma2(acc2[r][c], ap[r][1], bp23[c]);
            }
    }

    const int c0 = tx * 4, h = c0 >> 3, d0 = c0 & 7;
#pragma unroll
    for (int r = 0; r < 4; r++) {
        int gr = blk * 128 + ty * 4 + r;
        int b = gr >> 9, n = gr & 511;
        float o[4];
#pragma unroll
        for (int c = 0; c < 4; c++) o[c] = lof(acc2[r][c]) + hif(acc2[r][c]);
        *reinterpret_cast<float4*>(&g_Wh1[(((size_t)(b * NH + h)) * NN + n) * ND + d0]) =
            make_float4(o[0], o[1], o[2], o[3]);
    }
}

// =====================================================================
// kB: layer-1 attention per (b,h).  (Round-13 version)
// =====================================================================
struct K2S {
    float SUV[16 * 640];
    ull sbuf[2][NN];
    unsigned sortedA[NN];
    unsigned sortedB[NN];
    float E1s[NN], F1s[NN];
    float PE[NN], PF[NN];
    float wsum2[16][2], off2[16][2];
    float redbuf[16];
    float av[16];
    unsigned short rankB[NN];
};
__device__ __forceinline__ int suv_addr(int c, int r) {
    return c * 640 + (r >> 4) * 20 + (r & 15);
}

__device__ __forceinline__ void scan2b(float* A, float* B, float (*wsum2)[2],
                                       float (*off2)[2], int tid) {
    const int lane = tid & 31, wid = tid >> 5;
    float a = A[tid], b = B[tid];
#pragma unroll
    for (int s = 1; s < 32; s <<= 1) {
        float ta = __shfl_up_sync(0xffffffffu, a, s);
        float tb = __shfl_up_sync(0xffffffffu, b, s);
        if (lane >= s) { a += ta; b += tb; }
    }
    if (lane == 31) { wsum2[wid][0] = a; wsum2[wid][1] = b; }
    __syncthreads();
    if (wid < 2) {
        float x0 = (lane < 16) ? wsum2[lane][wid] : 0.f;
        float x = x0;
#pragma unroll
        for (int s = 1; s < 16; s <<= 1) {
            float tv = __shfl_up_sync(0xffffffffu, x, s);
            if (lane >= s) x += tv;
        }
        if (lane < 16) off2[lane][wid] = x - x0;
    }
    __syncthreads();
    A[tid] = a + off2[wid][0];
    B[tid] = b + off2[wid][1];
    __syncthreads();
}

__global__ __launch_bounds__(512, 2) void kB(const float* __restrict__ As_g) {
    extern __shared__ char raw[];
    K2S& S = *reinterpret_cast<K2S*>(raw);
    const int b = blockIdx.x, h = blockIdx.y, tid = threadIdx.x;
    const int lane = tid & 31, wid = tid >> 5;

    if (tid < 16) S.av[tid] = As_g[h * 16 + tid];

    const float4* whp = reinterpret_cast<const float4*>(
        g_Wh1 + (((size_t)(b * NH + h)) * NN + tid) * ND);
    float4 w0 = whp[0], w1 = whp[1];
    float wv[8] = {w0.x, w0.y, w0.z, w0.w, w1.x, w1.y, w1.z, w1.w};
    __syncthreads();

    float s1 = 0.f, s2 = 0.f;
#pragma unroll
    for (int d = 0; d < 8; d++) { s1 += wv[d] * S.av[d]; s2 += wv[d] * S.av[8 + d]; }
    const float s1L = s1 * LOG2E, s2L = s2 * LOG2E;

    float m = s1L;
#pragma unroll
    for (int o = 16; o >= 1; o >>= 1) m = fmaxf(m, __shfl_xor_sync(0xffffffffu, m, o));
    if (lane == 0) S.redbuf[wid] = m;
    __syncthreads();
    float M = S.redbuf[0];
#pragma unroll
    for (int w = 1; w < 16; w++) M = fmaxf(M, S.redbuf[w]);

    const float E1 = ex2f(s1L - M);
    const float F1 = ex2f(0.2f * (s1L - M));
    S.E1s[tid] = E1;
    S.F1s[tid] = F1;

    unsigned ka = (f2s(s1L) & KEYMASK) | (unsigned)tid;
    unsigned kb = (f2s(s2L) & KEYMASK) | (unsigned)tid;
    int p = 0;
    for (int k = 2; k <= NN; k <<= 1) {
        for (int s = k >> 1; s >= 1; s >>= 1) {
            const bool keepmin = (((tid & s) == 0) == ((tid & k) == 0));
            unsigned oa, ob;
            if (s >= 32) {
                S.sbuf[p][tid] = (((ull)ka) << 32) | kb;
                __syncthreads();
                ull o = S.sbuf[p][tid ^ s];
                oa = (unsigned)(o >> 32); ob = (unsigned)o;
                p ^= 1;
            } else {
                oa = __shfl_xor_sync(0xffffffffu, ka, s);
                ob = __shfl_xor_sync(0xffffffffu, kb, s);
            }
            ka = ((ka < oa) == keepmin) ? ka : oa;
            kb = ((kb < ob) == keepmin) ? kb : ob;
        }
    }
    S.sortedA[tid] = ka;
    S.sortedB[tid] = kb;
    {
        int ja = (int)(ka & 511u);
        int jb = (int)(kb & 511u);
        S.rankB[jb] = (unsigned short)tid;
        S.PE[tid] = S.E1s[ja];
        S.PF[tid] = S.F1s[ja];
    }
    __syncthreads();
    scan2b(S.PE, S.PF, S.wsum2, S.off2, tid);
    const float TE = S.PE[NN - 1];

    const int c = lb512(S.sortedA, f2s(-s2L) & KEYMASK);
    const float sumEge = TE - (c > 0 ? S.PE[c - 1] : 0.f);
    const float preF   = (c > 0 ? S.PF[c - 1] : 0.f);
    const float mj = lrelu02(M + s2L);
    const float E2 = ex2f(s2L + M - mj);
    const float F2 = ex2f(0.2f * (s2L + M) - mj);
    const float rz = 1.0f / (E2 * sumEge + F2 * preF);
    const float ue = E2 * rz, vf = F2 * rz;

    const int r = S.rankB[tid];
#pragma unroll
    for (int d = 0; d < 8; d++) {
        S.SUV[suv_addr(d, r)]     = ue * wv[d];
        S.SUV[suv_addr(8 + d, r)] = vf * wv[d];
    }
    __syncthreads();

    {
        float4* base = reinterpret_cast<float4*>(S.SUV) + wid * 160 + lane * 5;
        float4 q0 = base[0], q1 = base[1], q2 = base[2], q3 = base[3];
        float v[16] = {q0.x, q0.y, q0.z, q0.w, q1.x, q1.y, q1.z, q1.w,
                       q2.x, q2.y, q2.z, q2.w, q3.x, q3.y, q3.z, q3.w};
#pragma unroll
        for (int i = 1; i < 16; i++) v[i] += v[i - 1];
        float tot = v[15], inc = tot;
#pragma unroll
        for (int s = 1; s < 32; s <<= 1) {
            float tv = __shfl_up_sync(0xffffffffu, inc, s);
            if (lane >= s) inc += tv;
        }
        float off = inc - tot;
#pragma unroll
        for (int i = 0; i < 16; i++) v[i] += off;
        base[0] = make_float4(v[0], v[1], v[2], v[3]);
        base[1] = make_float4(v[4], v[5], v[6], v[7]);
        base[2] = make_float4(v[8], v[9], v[10], v[11]);
        base[3] = make_float4(v[12], v[13], v[14], v[15]);
    }
    __syncthreads();

    float TU[8];
#pragma unroll
    for (int d = 0; d < 8; d++) TU[d] = S.SUV[suv_addr(d, NN - 1)];

    const int c2 = lb512(S.sortedB, f2s(-s1L) & KEYMASK);
    float res[8];
#pragma unroll
    for (int d = 0; d < 8; d++) {
        float su = TU[d] - (c2 > 0 ? S.SUV[suv_addr(d, c2 - 1)] : 0.f);
        float pv = (c2 > 0 ? S.SUV[suv_addr(8 + d, c2 - 1)] : 0.f);
        res[d] = eluf(E1 * su + F1 * pv);
    }
    float4* xo = reinterpret_cast<float4*>(g_x + ((size_t)(b * NN + tid)) * (NH * ND) + h * ND);
    xo[0] = make_float4(res[0], res[1], res[2], res[3]);
    xo[1] = make_float4(res[4], res[5], res[6], res[7]);
}

// =====================================================================
// k34: layer-2 projection + attention (row 0), chunked over j.
// grid (32, 4), 512 threads; each block projects all 512 rows, sorts s1
// once, emits the partial weighted sum for its 128-j chunk.
// =====================================================================
__global__ __launch_bounds__(512) void k34(const float* __restrict__ Wout,
                                           const float* __restrict__ aout) {
    __shared__ float Wot[8][72];
    __shared__ float ao[16];
    __shared__ float whs[128][9];
    __shared__ float s2s[128];
    __shared__ unsigned sbufD[2][NN];
    __shared__ unsigned sortedA[NN];
    __shared__ float E1s[NN], F1s[NN], PE[NN], PF[NN];
    __shared__ float wsum2[16][2], off2[16][2];
    __shared__ float redbuf[16];
    __shared__ float wpart[4][8];
    __shared__ float bc0[1];

    const int b = blockIdx.x, jc = blockIdx.y, tid = threadIdx.x;
    const int lane = tid & 31, wid = tid >> 5;

    Wot[tid & 7][tid >> 3] = Wout[tid];
    if (tid < 16) ao[tid] = aout[tid];
    __syncthreads();

    // projection of row tid
    const float4* xr = reinterpret_cast<const float4*>(g_x + ((size_t)(b * NN + tid)) * 64);
    float4 xv[16];
#pragma unroll
    for (int q = 0; q < 16; q++) xv[q] = xr[q];
    ull xp[32];
#pragma unroll
    for (int q = 0; q < 16; q++) {
        xp[2 * q]     = packf2(xv[q].x, xv[q].y);
        xp[2 * q + 1] = packf2(xv[q].z, xv[q].w);
    }
    float acc[8];
#pragma unroll
    for (int d = 0; d < 8; d++) {
        ull a2 = 0ull;
#pragma unroll
        for (int q = 0; q < 16; q++) {
            float4 bq = *reinterpret_cast<const float4*>(&Wot[d][q * 4]);
            ffma2(a2, xp[2 * q], packf2(bq.x, bq.y));
            ffma2(a2, xp[2 * q + 1], packf2(bq.z, bq.w));
        }
        acc[d] = lof(a2) + hif(a2);
    }
    float s1 = 0.f, s2 = 0.f;
#pragma unroll
    for (int d = 0; d < 8; d++) { s1 += acc[d] * ao[d]; s2 += acc[d] * ao[8 + d]; }
    const float s1L = s1 * LOG2E, s2L = s2 * LOG2E;

    if ((tid >> 7) == jc) {
        const int jl = tid & 127;
        s2s[jl] = s2L;
#pragma unroll
        for (int d = 0; d < 8; d++) whs[jl][d] = acc[d];
    }
    if (tid == 0) bc0[0] = s1L;

    float m = s1L;
#pragma unroll
    for (int o = 16; o >= 1; o >>= 1) m = fmaxf(m, __shfl_xor_sync(0xffffffffu, m, o));
    if (lane == 0) redbuf[wid] = m;
    __syncthreads();
    float M = redbuf[0];
#pragma unroll
    for (int w = 1; w < 16; w++) M = fmaxf(M, redbuf[w]);

    E1s[tid] = ex2f(s1L - M);
    F1s[tid] = ex2f(0.2f * (s1L - M));

    unsigned ka = (f2s(s1L) & KEYMASK) | (unsigned)tid;
    int p = 0;
    for (int k = 2; k <= NN; k <<= 1) {
        for (int s = k >> 1; s >= 1; s >>= 1) {
            const bool keepmin = (((tid & s) == 0) == ((tid & k) == 0));
            unsigned oa;
            if (s >= 32) {
                sbufD[p][tid] = ka;
                __syncthreads();
                oa = sbufD[p][tid ^ s];
                p ^= 1;
            } else {
                oa = __shfl_xor_sync(0xffffffffu, ka, s);
            }
            ka = ((ka < oa) == keepmin) ? ka : oa;
        }
    }
    sortedA[tid] = ka;
    {
        int ja = (int)(ka & 511u);
        PE[tid] = E1s[ja];
        PF[tid] = F1s[ja];
    }
    __syncthreads();
    scan2b(PE, PF, wsum2, off2, tid);
    const float TE = PE[NN - 1];

    if (tid < 128) {
        const float s2j = s2s[tid];
        const int c = lb512(sortedA, f2s(-s2j) & KEYMASK);
        const float sumEge = TE - (c > 0 ? PE[c - 1] : 0.f);
        const float preF   = (c > 0 ? PF[c - 1] : 0.f);
        const float mj = lrelu02(M + s2j);
        const float E2 = ex2f(s2j + M - mj);
        const float F2 = ex2f(0.2f * (s2j + M) - mj);
        const float Z = E2 * sumEge + F2 * preF;

        const float s1L0 = bc0[0];
        const float e0 = (s1L0 + s2j >= 0.f) ? ex2f(s1L0 - M) * E2
                                             : ex2f(0.2f * (s1L0 - M)) * F2;
        const float wj = e0 / Z;

        float pv[8];
#pragma unroll
        for (int d = 0; d < 8; d++) pv[d] = wj * whs[tid][d];
#pragma unroll
        for (int d = 0; d < 8; d++) {
#pragma unroll
            for (int o = 16; o >= 1; o >>= 1)
                pv[d] += __shfl_xor_sync(0xffffffffu, pv[d], o);
        }
        if (lane == 0) {
#pragma unroll
            for (int d = 0; d < 8; d++) wpart[wid][d] = pv[d];
        }
    }
    __syncthreads();
    if (tid < 8) {
        g_h0p[b][jc][tid] = wpart[0][tid] + wpart[1][tid] + wpart[2][tid] + wpart[3][tid];
    }
}

// =====================================================================
// kE: elu(h0) -> concat feats -> lin1 -> prelu -> bn -> lin2
// =====================================================================
__global__ __launch_bounds__(256) void kE(const float* __restrict__ feats,
                                          const float* __restrict__ lin1w,
                                          const float* __restrict__ lin1b,
                                          const float* __restrict__ prelua,
                                          const float* __restrict__ gamma,
                                          const float* __restrict__ beta,
                                          const float* __restrict__ lin2w,
                                          const float* __restrict__ lin2b,
                                          float* __restrict__ out) {
    const int tid = threadIdx.x;
    const int b = tid >> 3, k = tid & 7;

    float gat[8];
#pragma unroll
    for (int d = 0; d < 8; d++) {
        float v = g_h0p[b][0][d] + g_h0p[b][1][d] + g_h0p[b][2][d] + g_h0p[b][3][d];
        gat[d] = eluf(v);
    }

    const float* w = lin1w + k * 136;
    const float* fr = feats + b * 128;
    float z = lin1b[k];
#pragma unroll 8
    for (int f = 0; f < 128; f++) z += fr[f] * w[f];
#pragma unroll
    for (int d = 0; d < 8; d++) z += gat[d] * w[128 + d];

    const float pa = prelua[0];
    z = (z >= 0.f) ? z : pa * z;
    z = z * rsqrtf(1.0f + 1e-5f) * gamma[k] + beta[k];

    float v = z * lin2w[k];
    v += __shfl_xor_sync(0xffffffffu, v, 4);
    v += __shfl_xor_sync(0xffffffffu, v, 2);
    v += __shfl_xor_sync(0xffffffffu, v, 1);
    if (k == 0) out[b] = v + lin2b[0];
}

// =====================================================================
extern "C" void kernel_launch(void* const* d_in, const int* in_sizes, int n_in,
                              void* d_out, int out_size) {
    (void)in_sizes; (void)n_in; (void)out_size;
    const float* feats  = (const float*)d_in[0];
    const float* nf     = (const float*)d_in[1];
    const float* Ws     = (const float*)d_in[2];
    const float* As     = (const float*)d_in[3];
    const float* Wout   = (const float*)d_in[4];
    const float* aout   = (const float*)d_in[5];
    const float* lin1w  = (const float*)d_in[6];
    const float* lin1b  = (const float*)d_in[7];
    const float* prelua = (const float*)d_in[8];
    const float* gamma  = (const float*)d_in[9];
    const float* beta   = (const float*)d_in[10];
    const float* lin2w  = (const float*)d_in[11];
    const float* lin2b  = (const float*)d_in[12];
    float* out = (float*)d_out;

    static bool attr_done = false;
    if (!attr_done) {
        cudaFuncSetAttribute(kA, cudaFuncAttributeMaxDynamicSharedMemorySize, KA_SMEM);
        cudaFuncSetAttribute(kB, cudaFuncAttributeMaxDynamicSharedMemorySize,
                             (int)sizeof(K2S));
        attr_done = true;
    }

    kA<<<128, 512, KA_SMEM>>>(nf, Ws);
    kB<<<dim3(32, 8), 512, sizeof(K2S)>>>(As);
    k34<<<dim3(32, 4), 512>>>(Wout, aout);
    kE<<<1, 256>>>(feats, lin1w, lin1b, prelua, gamma, beta, lin2w, lin2b, out);
}

// round 16
// speedup vs baseline: 1.4668x; 1.0957x over previous
#include <cuda_runtime.h>

typedef unsigned long long ull;

#define LOG2E 1.4426950408889634f
#define BB 32
#define NN 512
#define NH 8
#define ND 8
#define NF 128
#define KEYMASK 0xFFFFFE00u

// ---------------- scratch ----------------
__device__ float g_Wh1[BB * NH * NN * ND];   // [b][h][n][d]
__device__ float g_x[BB * NN * NH * ND];     // [b][n][h*8+d]
__device__ float g_h0p[BB][4][ND];           // layer-2 per-chunk partials

// ---------------- helpers ----------------
__device__ __forceinline__ float ex2f(float x) {
    float r; asm("ex2.approx.f32 %0, %1;" : "=f"(r) : "f"(x)); return r;
}
__device__ __forceinline__ void ffma2(ull &acc, ull a, ull b) {
    asm("fma.rn.f32x2 %0, %1, %2, %0;" : "+l"(acc) : "l"(a), "l"(b));
}
__device__ __forceinline__ ull packf2(float lo, float hi) {
    ull r; asm("mov.b64 %0, {%1, %2};" : "=l"(r) : "f"(lo), "f"(hi)); return r;
}
__device__ __forceinline__ float lof(ull v) { return __uint_as_float((unsigned)(v & 0xffffffffu)); }
__device__ __forceinline__ float hif(ull v) { return __uint_as_float((unsigned)(v >> 32)); }
__device__ __forceinline__ float lrelu02(float x) { return fmaxf(x, 0.2f * x); }
__device__ __forceinline__ float eluf(float x) { return x > 0.f ? x : ex2f(x * LOG2E) - 1.0f; }
__device__ __forceinline__ unsigned f2s(float f) {
    unsigned u = __float_as_uint(f);
    return u ^ ((u & 0x80000000u) ? 0xFFFFFFFFu : 0x80000000u);
}
__device__ __forceinline__ int lb512(const unsigned* arr, unsigned X) {
    int c = 0;
#pragma unroll
    for (int s = 512; s >= 1; s >>= 1) {
        int t = c + s;
        if (t <= 512 && arr[t - 1] < X) c = t;
    }
    return c;
}

// =====================================================================
// kA: Wh = nf @ W  as [16384,128]@[128,64] GEMM.  (Round-13 version)
// =====================================================================
#define KA_BSTRIDE 10
#define KA_SMEM (128 * 128 * 4 + 32 * 16 * KA_BSTRIDE * 8)
__global__ __launch_bounds__(512) void kA(const float* __restrict__ nf,
                                          const float* __restrict__ Ws) {
    extern __shared__ float sm[];
    float* As = sm;
    ull* Bp = reinterpret_cast<ull*>(sm + 128 * 128);
    const int t = threadIdx.x, blk = blockIdx.x;

    const float4* gA = reinterpret_cast<const float4*>(nf) + (size_t)blk * 128 * 32;
    float4* As4 = reinterpret_cast<float4*>(As);
#pragma unroll
    for (int i = 0; i < 8; i++) {
        int idx4 = t + 512 * i;
        As4[idx4] = gA[idx4];
    }
#pragma unroll
    for (int i = 0; i < 8; i++) {
        int idx = t + 512 * i;
        int k4 = idx >> 7, rem = idx & 127;
        int tx = rem >> 3, s = rem & 7;
        int c = 4 * tx + (s & 3);
        int kk = 4 * k4 + 2 * (s >> 2);
        const float* wsrc = Ws + (c >> 3) * 1024 + kk * 8 + (c & 7);
        Bp[(k4 * 16 + tx) * KA_BSTRIDE + s] = packf2(wsrc[0], wsrc[8]);
    }
    __syncthreads();

    const int tx = t & 15, ty = t >> 4;
    ull acc2[4][4];
#pragma unroll
    for (int r = 0; r < 4; r++)
#pragma unroll
        for (int c = 0; c < 4; c++) acc2[r][c] = 0ull;

#pragma unroll 8
    for (int k4 = 0; k4 < 32; k4++) {
        ull ap[4][2];
#pragma unroll
        for (int r = 0; r < 4; r++) {
            float4 a = *reinterpret_cast<const float4*>(&As[(ty * 4 + r) * 128 + k4 * 4]);
            ap[r][0] = packf2(a.x, a.y);
            ap[r][1] = packf2(a.z, a.w);
        }
        const ull* bb = Bp + (k4 * 16 + tx) * KA_BSTRIDE;
        ulonglong2 u0 = *reinterpret_cast<const ulonglong2*>(bb + 0);
        ulonglong2 u1 = *reinterpret_cast<const ulonglong2*>(bb + 2);
        ulonglong2 u2 = *reinterpret_cast<const ulonglong2*>(bb + 4);
        ulonglong2 u3 = *reinterpret_cast<const ulonglong2*>(bb + 6);
        ull bp01[4] = {u0.x, u0.y, u1.x, u1.y};
        ull bp23[4] = {u2.x, u2.y, u3.x, u3.y};
#pragma unroll
        for (int r = 0; r < 4; r++)
#pragma unroll
            for (int c = 0; c < 4; c++) {
                ffma2(acc2[r][c], ap[r][0], bp01[c]);
                ffma2(acc2[r][c], ap[r][1], bp23[c]);
            }
    }

    const int c0 = tx * 4, h = c0 >> 3, d0 = c0 & 7;
#pragma unroll
    for (int r = 0; r < 4; r++) {
        int gr = blk * 128 + ty * 4 + r;
        int b = gr >> 9, n = gr & 511;
        float o[4];
#pragma unroll
        for (int c = 0; c < 4; c++) o[c] = lof(acc2[r][c]) + hif(acc2[r][c]);
        *reinterpret_cast<float4*>(&g_Wh1[(((size_t)(b * NH + h)) * NN + n) * ND + d0]) =
            make_float4(o[0], o[1], o[2], o[3]);
    }
}

// =====================================================================
// kB: layer-1 attention per (b,h).  (Round-13 version)
// =====================================================================
struct K2S {
    float SUV[16 * 640];
    ull sbuf[2][NN];
    unsigned sortedA[NN];
    unsigned sortedB[NN];
    float E1s[NN], F1s[NN];
    float PE[NN], PF[NN];
    float wsum2[16][2], off2[16][2];
    float redbuf[16];
    float av[16];
    unsigned short rankB[NN];
};
__device__ __forceinline__ int suv_addr(int c, int r) {
    return c * 640 + (r >> 4) * 20 + (r & 15);
}

__device__ __forceinline__ void scan2b(float* A, float* B, float (*wsum2)[2],
                                       float (*off2)[2], int tid) {
    const int lane = tid & 31, wid = tid >> 5;
    float a = A[tid], b = B[tid];
#pragma unroll
    for (int s = 1; s < 32; s <<= 1) {
        float ta = __shfl_up_sync(0xffffffffu, a, s);
        float tb = __shfl_up_sync(0xffffffffu, b, s);
        if (lane >= s) { a += ta; b += tb; }
    }
    if (lane == 31) { wsum2[wid][0] = a; wsum2[wid][1] = b; }
    __syncthreads();
    if (wid < 2) {
        float x0 = (lane < 16) ? wsum2[lane][wid] : 0.f;
        float x = x0;
#pragma unroll
        for (int s = 1; s < 16; s <<= 1) {
            float tv = __shfl_up_sync(0xffffffffu, x, s);
            if (lane >= s) x += tv;
        }
        if (lane < 16) off2[lane][wid] = x - x0;
    }
    __syncthreads();
    A[tid] = a + off2[wid][0];
    B[tid] = b + off2[wid][1];
    __syncthreads();
}

__global__ __launch_bounds__(512, 2) void kB(const float* __restrict__ As_g) {
    extern __shared__ char raw[];
    K2S& S = *reinterpret_cast<K2S*>(raw);
    const int b = blockIdx.x, h = blockIdx.y, tid = threadIdx.x;
    const int lane = tid & 31, wid = tid >> 5;

    if (tid < 16) S.av[tid] = As_g[h * 16 + tid];

    const float4* whp = reinterpret_cast<const float4*>(
        g_Wh1 + (((size_t)(b * NH + h)) * NN + tid) * ND);
    float4 w0 = whp[0], w1 = whp[1];
    float wv[8] = {w0.x, w0.y, w0.z, w0.w, w1.x, w1.y, w1.z, w1.w};
    __syncthreads();

    float s1 = 0.f, s2 = 0.f;
#pragma unroll
    for (int d = 0; d < 8; d++) { s1 += wv[d] * S.av[d]; s2 += wv[d] * S.av[8 + d]; }
    const float s1L = s1 * LOG2E, s2L = s2 * LOG2E;

    float m = s1L;
#pragma unroll
    for (int o = 16; o >= 1; o >>= 1) m = fmaxf(m, __shfl_xor_sync(0xffffffffu, m, o));
    if (lane == 0) S.redbuf[wid] = m;
    __syncthreads();
    float M = S.redbuf[0];
#pragma unroll
    for (int w = 1; w < 16; w++) M = fmaxf(M, S.redbuf[w]);

    const float E1 = ex2f(s1L - M);
    const float F1 = ex2f(0.2f * (s1L - M));
    S.E1s[tid] = E1;
    S.F1s[tid] = F1;

    unsigned ka = (f2s(s1L) & KEYMASK) | (unsigned)tid;
    unsigned kb = (f2s(s2L) & KEYMASK) | (unsigned)tid;
    int p = 0;
    for (int k = 2; k <= NN; k <<= 1) {
        for (int s = k >> 1; s >= 1; s >>= 1) {
            const bool keepmin = (((tid & s) == 0) == ((tid & k) == 0));
            unsigned oa, ob;
            if (s >= 32) {
                S.sbuf[p][tid] = (((ull)ka) << 32) | kb;
                __syncthreads();
                ull o = S.sbuf[p][tid ^ s];
                oa = (unsigned)(o >> 32); ob = (unsigned)o;
                p ^= 1;
            } else {
                oa = __shfl_xor_sync(0xffffffffu, ka, s);
                ob = __shfl_xor_sync(0xffffffffu, kb, s);
            }
            ka = ((ka < oa) == keepmin) ? ka : oa;
            kb = ((kb < ob) == keepmin) ? kb : ob;
        }
    }
    S.sortedA[tid] = ka;
    S.sortedB[tid] = kb;
    {
        int ja = (int)(ka & 511u);
        int jb = (int)(kb & 511u);
        S.rankB[jb] = (unsigned short)tid;
        S.PE[tid] = S.E1s[ja];
        S.PF[tid] = S.F1s[ja];
    }
    __syncthreads();
    scan2b(S.PE, S.PF, S.wsum2, S.off2, tid);
    const float TE = S.PE[NN - 1];

    const int c = lb512(S.sortedA, f2s(-s2L) & KEYMASK);
    const float sumEge = TE - (c > 0 ? S.PE[c - 1] : 0.f);
    const float preF   = (c > 0 ? S.PF[c - 1] : 0.f);
    const float mj = lrelu02(M + s2L);
    const float E2 = ex2f(s2L + M - mj);
    const float F2 = ex2f(0.2f * (s2L + M) - mj);
    const float rz = 1.0f / (E2 * sumEge + F2 * preF);
    const float ue = E2 * rz, vf = F2 * rz;

    const int r = S.rankB[tid];
#pragma unroll
    for (int d = 0; d < 8; d++) {
        S.SUV[suv_addr(d, r)]     = ue * wv[d];
        S.SUV[suv_addr(8 + d, r)] = vf * wv[d];
    }
    __syncthreads();

    {
        float4* base = reinterpret_cast<float4*>(S.SUV) + wid * 160 + lane * 5;
        float4 q0 = base[0], q1 = base[1], q2 = base[2], q3 = base[3];
        float v[16] = {q0.x, q0.y, q0.z, q0.w, q1.x, q1.y, q1.z, q1.w,
                       q2.x, q2.y, q2.z, q2.w, q3.x, q3.y, q3.z, q3.w};
#pragma unroll
        for (int i = 1; i < 16; i++) v[i] += v[i - 1];
        float tot = v[15], inc = tot;
#pragma unroll
        for (int s = 1; s < 32; s <<= 1) {
            float tv = __shfl_up_sync(0xffffffffu, inc, s);
            if (lane >= s) inc += tv;
        }
        float off = inc - tot;
#pragma unroll
        for (int i = 0; i < 16; i++) v[i] += off;
        base[0] = make_float4(v[0], v[1], v[2], v[3]);
        base[1] = make_float4(v[4], v[5], v[6], v[7]);
        base[2] = make_float4(v[8], v[9], v[10], v[11]);
        base[3] = make_float4(v[12], v[13], v[14], v[15]);
    }
    __syncthreads();

    float TU[8];
#pragma unroll
    for (int d = 0; d < 8; d++) TU[d] = S.SUV[suv_addr(d, NN - 1)];

    const int c2 = lb512(S.sortedB, f2s(-s1L) & KEYMASK);
    float res[8];
#pragma unroll
    for (int d = 0; d < 8; d++) {
        float su = TU[d] - (c2 > 0 ? S.SUV[suv_addr(d, c2 - 1)] : 0.f);
        float pv = (c2 > 0 ? S.SUV[suv_addr(8 + d, c2 - 1)] : 0.f);
        res[d] = eluf(E1 * su + F1 * pv);
    }
    float4* xo = reinterpret_cast<float4*>(g_x + ((size_t)(b * NN + tid)) * (NH * ND) + h * ND);
    xo[0] = make_float4(res[0], res[1], res[2], res[3]);
    xo[1] = make_float4(res[4], res[5], res[6], res[7]);
}

// =====================================================================
// k34: layer-2 projection + attention (row 0), chunked over j.
// grid (32, 4), 512 threads.
// =====================================================================
__global__ __launch_bounds__(512) void k34(const float* __restrict__ Wout,
                                           const float* __restrict__ aout) {
    __shared__ float Wot[8][72];
    __shared__ float ao[16];
    __shared__ float whs[128][9];
    __shared__ float s2s[128];
    __shared__ unsigned sbufD[2][NN];
    __shared__ unsigned sortedA[NN];
    __shared__ float E1s[NN], F1s[NN], PE[NN], PF[NN];
    __shared__ float wsum2[16][2], off2[16][2];
    __shared__ float redbuf[16];
    __shared__ float wpart[4][8];
    __shared__ float bc0[1];

    const int b = blockIdx.x, jc = blockIdx.y, tid = threadIdx.x;
    const int lane = tid & 31, wid = tid >> 5;

    Wot[tid & 7][tid >> 3] = Wout[tid];
    if (tid < 16) ao[tid] = aout[tid];
    __syncthreads();

    const float4* xr = reinterpret_cast<const float4*>(g_x + ((size_t)(b * NN + tid)) * 64);
    float4 xv[16];
#pragma unroll
    for (int q = 0; q < 16; q++) xv[q] = xr[q];
    ull xp[32];
#pragma unroll
    for (int q = 0; q < 16; q++) {
        xp[2 * q]     = packf2(xv[q].x, xv[q].y);
        xp[2 * q + 1] = packf2(xv[q].z, xv[q].w);
    }
    float acc[8];
#pragma unroll
    for (int d = 0; d < 8; d++) {
        ull a2 = 0ull;
#pragma unroll
        for (int q = 0; q < 16; q++) {
            float4 bq = *reinterpret_cast<const float4*>(&Wot[d][q * 4]);
            ffma2(a2, xp[2 * q], packf2(bq.x, bq.y));
            ffma2(a2, xp[2 * q + 1], packf2(bq.z, bq.w));
        }
        acc[d] = lof(a2) + hif(a2);
    }
    float s1 = 0.f, s2 = 0.f;
#pragma unroll
    for (int d = 0; d < 8; d++) { s1 += acc[d] * ao[d]; s2 += acc[d] * ao[8 + d]; }
    const float s1L = s1 * LOG2E, s2L = s2 * LOG2E;

    if ((tid >> 7) == jc) {
        const int jl = tid & 127;
        s2s[jl] = s2L;
#pragma unroll
        for (int d = 0; d < 8; d++) whs[jl][d] = acc[d];
    }
    if (tid == 0) bc0[0] = s1L;

    float m = s1L;
#pragma unroll
    for (int o = 16; o >= 1; o >>= 1) m = fmaxf(m, __shfl_xor_sync(0xffffffffu, m, o));
    if (lane == 0) redbuf[wid] = m;
    __syncthreads();
    float M = redbuf[0];
#pragma unroll
    for (int w = 1; w < 16; w++) M = fmaxf(M, redbuf[w]);

    E1s[tid] = ex2f(s1L - M);
    F1s[tid] = ex2f(0.2f * (s1L - M));

    unsigned ka = (f2s(s1L) & KEYMASK) | (unsigned)tid;
    int p = 0;
    for (int k = 2; k <= NN; k <<= 1) {
        for (int s = k >> 1; s >= 1; s >>= 1) {
            const bool keepmin = (((tid & s) == 0) == ((tid & k) == 0));
            unsigned oa;
            if (s >= 32) {
                sbufD[p][tid] = ka;
                __syncthreads();
                oa = sbufD[p][tid ^ s];
                p ^= 1;
            } else {
                oa = __shfl_xor_sync(0xffffffffu, ka, s);
            }
            ka = ((ka < oa) == keepmin) ? ka : oa;
        }
    }
    sortedA[tid] = ka;
    {
        int ja = (int)(ka & 511u);
        PE[tid] = E1s[ja];
        PF[tid] = F1s[ja];
    }
    __syncthreads();
    scan2b(PE, PF, wsum2, off2, tid);
    const float TE = PE[NN - 1];

    if (tid < 128) {
        const float s2j = s2s[tid];
        const int c = lb512(sortedA, f2s(-s2j) & KEYMASK);
        const float sumEge = TE - (c > 0 ? PE[c - 1] : 0.f);
        const float preF   = (c > 0 ? PF[c - 1] : 0.f);
        const float mj = lrelu02(M + s2j);
        const float E2 = ex2f(s2j + M - mj);
        const float F2 = ex2f(0.2f * (s2j + M) - mj);
        const float Z = E2 * sumEge + F2 * preF;

        const float s1L0 = bc0[0];
        const float e0 = (s1L0 + s2j >= 0.f) ? ex2f(s1L0 - M) * E2
                                             : ex2f(0.2f * (s1L0 - M)) * F2;
        const float wj = e0 / Z;

        float pv[8];
#pragma unroll
        for (int d = 0; d < 8; d++) pv[d] = wj * whs[tid][d];
#pragma unroll
        for (int d = 0; d < 8; d++) {
#pragma unroll
            for (int o = 16; o >= 1; o >>= 1)
                pv[d] += __shfl_xor_sync(0xffffffffu, pv[d], o);
        }
        if (lane == 0) {
#pragma unroll
            for (int d = 0; d < 8; d++) wpart[wid][d] = pv[d];
        }
    }
    __syncthreads();
    if (tid < 8) {
        g_h0p[b][jc][tid] = wpart[0][tid] + wpart[1][tid] + wpart[2][tid] + wpart[3][tid];
    }
}

// =====================================================================
// kE: elu(h0) -> concat feats -> lin1 -> prelu -> bn -> lin2
// grid 32 (block per batch), 256 threads: warp k = output unit k.
// Lane-parallel loads kill the serial DRAM-latency chain.
// =====================================================================
__global__ __launch_bounds__(256) void kE(const float* __restrict__ feats,
                                          const float* __restrict__ lin1w,
                                          const float* __restrict__ lin1b,
                                          const float* __restrict__ prelua,
                                          const float* __restrict__ gamma,
                                          const float* __restrict__ beta,
                                          const float* __restrict__ lin2w,
                                          const float* __restrict__ lin2b,
                                          float* __restrict__ out) {
    __shared__ float hsum[8];
    __shared__ float zk[8];
    const int b = blockIdx.x;
    const int tid = threadIdx.x, lane = tid & 31, k = tid >> 5;

    if (tid < 8) {
        float v = g_h0p[b][0][tid] + g_h0p[b][1][tid] + g_h0p[b][2][tid] + g_h0p[b][3][tid];
        hsum[tid] = eluf(v);
    }
    __syncthreads();

    // warp k: dot(feats[b,:], lin1w[k,0:128]) with one float4 per lane
    const float4 fv = reinterpret_cast<const float4*>(feats + b * 128)[lane];
    const float* w = lin1w + k * 136;
    const float4 wv4 = reinterpret_cast<const float4*>(w)[lane];
    float z = fv.x * wv4.x + fv.y * wv4.y + fv.z * wv4.z + fv.w * wv4.w;
#pragma unroll
    for (int o = 16; o >= 1; o >>= 1) z += __shfl_xor_sync(0xffffffffu, z, o);

    if (lane == 0) {
        z += lin1b[k];
#pragma unroll
        for (int d = 0; d < 8; d++) z += hsum[d] * w[128 + d];
        const float pa = prelua[0];
        z = (z >= 0.f) ? z : pa * z;
        z = z * rsqrtf(1.0f + 1e-5f) * gamma[k] + beta[k];
        zk[k] = z * lin2w[k];
    }
    __syncthreads();
    if (tid == 0) {
        float v = lin2b[0];
#pragma unroll
        for (int q = 0; q < 8; q++) v += zk[q];
        out[b] = v;
    }
}

// =====================================================================
extern "C" void kernel_launch(void* const* d_in, const int* in_sizes, int n_in,
                              void* d_out, int out_size) {
    (void)in_sizes; (void)n_in; (void)out_size;
    const float* feats  = (const float*)d_in[0];
    const float* nf     = (const float*)d_in[1];
    const float* Ws     = (const float*)d_in[2];
    const float* As     = (const float*)d_in[3];
    const float* Wout   = (const float*)d_in[4];
    const float* aout   = (const float*)d_in[5];
    const float* lin1w  = (const float*)d_in[6];
    const float* lin1b  = (const float*)d_in[7];
    const float* prelua = (const float*)d_in[8];
    const float* gamma  = (const float*)d_in[9];
    const float* beta   = (const float*)d_in[10];
    const float* lin2w  = (const float*)d_in[11];
    const float* lin2b  = (const float*)d_in[12];
    float* out = (float*)d_out;

    static bool attr_done = false;
    if (!attr_done) {
        cudaFuncSetAttribute(kA, cudaFuncAttributeMaxDynamicSharedMemorySize, KA_SMEM);
        cudaFuncSetAttribute(kB, cudaFuncAttributeMaxDynamicSharedMemorySize,
                             (int)sizeof(K2S));
        attr_done = true;
    }

    kA<<<128, 512, KA_SMEM>>>(nf, Ws);
    kB<<<dim3(32, 8), 512, sizeof(K2S)>>>(As);
    k34<<<dim3(32, 4), 512>>>(Wout, aout);
    kE<<<32, 256>>>(feats, lin1w, lin1b, prelua, gamma, beta, lin2w, lin2b, out);
}